// round 1
// baseline (speedup 1.0000x reference)
#include <cuda_runtime.h>
#include <math.h>

#define NB      16
#define LLEN    160000
#define NT      1603
#define CR      257
#define KLEN    400
#define STRIDE  100
#define PADL    300
#define BT      64          // frames per block tile
#define BCH     64          // real-channel rows per block tile (imag fused)
#define KC      40          // K chunk
#define XS_LEN  ((BT - 1) * STRIDE + KLEN)   // 6700
#define EPSV    1.1920928955078125e-07f

__device__ __forceinline__ unsigned long long pack2(float a, float b) {
    unsigned long long r;
    asm("mov.b64 %0, {%1, %2};" : "=l"(r) : "f"(a), "f"(b));
    return r;
}

__device__ __forceinline__ void fma2(unsigned long long& d,
                                     unsigned long long a,
                                     unsigned long long b) {
    asm("fma.rn.f32x2 %0, %1, %2, %0;" : "+l"(d) : "l"(a), "l"(b));
}

__device__ __forceinline__ float2 unpack2(unsigned long long v) {
    float2 r;
    asm("mov.b64 {%0, %1}, %2;" : "=f"(r.x), "=f"(r.y) : "l"(v));
    return r;
}

__global__ __launch_bounds__(256)
void convstft_kernel(const float* __restrict__ inp,
                     const float* __restrict__ wgt,
                     float* __restrict__ out)
{
    __shared__ __align__(16) float xs[XS_LEN];
    __shared__ __align__(16) float wr[KC][BCH + 4];   // [k][c], pad to 68 to break conflicts
    __shared__ __align__(16) float wi[KC][BCH + 4];

    const int tid = threadIdx.x;
    const int tx  = tid & 15;        // frame lane
    const int ty  = tid >> 4;        // channel group
    const int ty4 = ty * 4;
    const int t0  = blockIdx.x * BT;
    const int c0  = blockIdx.y * BCH;
    const int b   = blockIdx.z;

    // ---- stage input window for this frame tile ----
    const int gbase = t0 * STRIDE - PADL;
    const float* xin = inp + (size_t)b * LLEN;
    for (int i = tid; i < XS_LEN; i += 256) {
        int g = gbase + i;
        xs[i] = (g >= 0 && g < LLEN) ? xin[g] : 0.0f;
    }

    // accumulators: 4 frames (stride-16 lanes) x 2 channel-pairs, real+imag
    unsigned long long accR[4][2], accI[4][2];
#pragma unroll
    for (int j = 0; j < 4; ++j) {
        accR[j][0] = 0ull; accR[j][1] = 0ull;
        accI[j][0] = 0ull; accI[j][1] = 0ull;
    }

    int xb[4];
#pragma unroll
    for (int j = 0; j < 4; ++j) xb[j] = (tx + 16 * j) * STRIDE;

    for (int kk = 0; kk < KLEN; kk += KC) {
        __syncthreads();   // also covers xs on first pass; protects wr/wi reuse after
        // ---- stage weight chunk, transposed to [k][c] ----
        for (int i = tid; i < BCH * (KC / 4); i += 256) {  // 640 float4 per half
            int row = i / (KC / 4);
            int q   = i - row * (KC / 4);
            int c   = c0 + row;
            float4 vr = make_float4(0.f, 0.f, 0.f, 0.f);
            float4 vi = vr;
            if (c < CR) {
                vr = *(const float4*)(wgt + (size_t)c        * KLEN + kk + q * 4);
                vi = *(const float4*)(wgt + (size_t)(c + CR) * KLEN + kk + q * 4);
            }
            int kb = q * 4;
            wr[kb + 0][row] = vr.x; wr[kb + 1][row] = vr.y;
            wr[kb + 2][row] = vr.z; wr[kb + 3][row] = vr.w;
            wi[kb + 0][row] = vi.x; wi[kb + 1][row] = vi.y;
            wi[kb + 2][row] = vi.z; wi[kb + 3][row] = vi.w;
        }
        __syncthreads();

#pragma unroll 4
        for (int k = 0; k < KC; ++k) {
            // two f32x2 channel pairs per half, straight from one LDS.128
            ulonglong2 wrv = *(const ulonglong2*)&wr[k][ty4];
            ulonglong2 wiv = *(const ulonglong2*)&wi[k][ty4];
#pragma unroll
            for (int j = 0; j < 4; ++j) {
                float xv = xs[xb[j] + kk + k];
                unsigned long long x2 = pack2(xv, xv);
                fma2(accR[j][0], x2, wrv.x);
                fma2(accR[j][1], x2, wrv.y);
                fma2(accI[j][0], x2, wiv.x);
                fma2(accI[j][1], x2, wiv.y);
            }
        }
    }

    // ---- fused epilogue: mags + phase ----
    const size_t phoff = (size_t)NB * CR * NT;
#pragma unroll
    for (int j = 0; j < 4; ++j) {
        int t = t0 + tx + 16 * j;
        if (t >= NT) continue;
#pragma unroll
        for (int p = 0; p < 2; ++p) {
            float2 rv = unpack2(accR[j][p]);
            float2 iv = unpack2(accI[j][p]);
            float rr[2] = {rv.x, rv.y};
            float ii[2] = {iv.x, iv.y};
#pragma unroll
            for (int m = 0; m < 2; ++m) {
                int c = c0 + ty4 + p * 2 + m;
                if (c < CR) {
                    size_t o = ((size_t)b * CR + c) * (size_t)NT + (size_t)t;
                    float r_ = rr[m], i_ = ii[m];
                    out[o]         = sqrtf(fmaxf(r_ * r_ + i_ * i_, EPSV));
                    out[phoff + o] = atan2f(i_ + EPSV, r_ + EPSV);
                }
            }
        }
    }
}

extern "C" void kernel_launch(void* const* d_in, const int* in_sizes, int n_in,
                              void* d_out, int out_size) {
    const float* inp = (const float*)d_in[0];   // (16, 160000) fp32
    const float* wgt = (const float*)d_in[1];   // (514, 1, 400) fp32
    float* out = (float*)d_out;                 // mags ++ phase, fp32

    dim3 grid((NT + BT - 1) / BT,               // 26 frame tiles
              (CR + BCH - 1) / BCH,             // 5 channel tiles
              NB);                              // 16 batches
    convstft_kernel<<<grid, 256>>>(inp, wgt, out);
}

// round 2
// speedup vs baseline: 1.0279x; 1.0279x over previous
#include <cuda_runtime.h>
#include <math.h>

#define NB      16
#define LLEN    160000
#define NT      1603
#define CR      257
#define KLEN    400
#define STRIDE  100
#define PADL    300
#define BT      64          // frames per block tile
#define BCH     64          // real-channel rows per block tile (imag fused)
#define KC      40          // K chunk
#define XS_LEN  ((BT - 1) * STRIDE + KLEN)   // 6700
#define EPSV    1.1920928955078125e-07f

__device__ __forceinline__ unsigned long long packdup(float a) {
    unsigned long long r;
    asm("mov.b64 %0, {%1, %1};" : "=l"(r) : "f"(a));
    return r;
}

__device__ __forceinline__ void fma2(unsigned long long& d,
                                     unsigned long long a,
                                     unsigned long long b) {
    asm("fma.rn.f32x2 %0, %1, %2, %0;" : "+l"(d) : "l"(a), "l"(b));
}

__device__ __forceinline__ float2 unpack2(unsigned long long v) {
    float2 r;
    asm("mov.b64 {%0, %1}, %2;" : "=f"(r.x), "=f"(r.y) : "l"(v));
    return r;
}

__global__ __launch_bounds__(256)
void convstft_kernel(const float* __restrict__ inp,
                     const float* __restrict__ wgt,
                     float* __restrict__ out)
{
    __shared__ __align__(16) float xs[XS_LEN];
    __shared__ __align__(16) float wr[KC][BCH + 4];   // [k][c], pad 68 floats
    __shared__ __align__(16) float wi[KC][BCH + 4];

    const int tid = threadIdx.x;
    const int tx  = tid & 15;        // frame lane
    const int ty  = tid >> 4;        // channel group
    const int ty4 = ty * 4;
    const int t0  = blockIdx.x * BT;
    const int c0  = blockIdx.y * BCH;
    const int b   = blockIdx.z;

    // ---- stage input window for this frame tile ----
    const int gbase = t0 * STRIDE - PADL;
    const float* xin = inp + (size_t)b * LLEN;
    for (int i = tid; i < XS_LEN; i += 256) {
        int g = gbase + i;
        xs[i] = (g >= 0 && g < LLEN) ? xin[g] : 0.0f;
    }

    // accumulators: 4 frames (stride-16 lanes) x 2 channel-pairs, real+imag
    unsigned long long accR[4][2], accI[4][2];
#pragma unroll
    for (int j = 0; j < 4; ++j) {
        accR[j][0] = 0ull; accR[j][1] = 0ull;
        accI[j][0] = 0ull; accI[j][1] = 0ull;
    }

    int xb[4];
#pragma unroll
    for (int j = 0; j < 4; ++j) xb[j] = (tx + 16 * j) * STRIDE;

    for (int kk = 0; kk < KLEN; kk += KC) {
        __syncthreads();   // covers xs on first pass; protects wr/wi reuse after
        // ---- stage weight chunk, transposed to [k][c] ----
        for (int i = tid; i < BCH * (KC / 4); i += 256) {  // 640 float4 per half
            int row = i / (KC / 4);
            int q   = i - row * (KC / 4);
            int c   = c0 + row;
            float4 vr = make_float4(0.f, 0.f, 0.f, 0.f);
            float4 vi = vr;
            if (c < CR) {
                vr = *(const float4*)(wgt + (size_t)c        * KLEN + kk + q * 4);
                vi = *(const float4*)(wgt + (size_t)(c + CR) * KLEN + kk + q * 4);
            }
            int kb = q * 4;
            wr[kb + 0][row] = vr.x; wr[kb + 1][row] = vr.y;
            wr[kb + 2][row] = vr.z; wr[kb + 3][row] = vr.w;
            wi[kb + 0][row] = vi.x; wi[kb + 1][row] = vi.y;
            wi[kb + 2][row] = vi.z; wi[kb + 3][row] = vi.w;
        }
        __syncthreads();

#pragma unroll 2
        for (int k4 = 0; k4 < KC; k4 += 4) {
            // one vector load of x per frame covers 4 consecutive k
            float4 xq[4];
#pragma unroll
            for (int j = 0; j < 4; ++j)
                xq[j] = *(const float4*)&xs[xb[j] + kk + k4];

#pragma unroll
            for (int kz = 0; kz < 4; ++kz) {
                const int k = k4 + kz;
                ulonglong2 wrv = *(const ulonglong2*)&wr[k][ty4];
                ulonglong2 wiv = *(const ulonglong2*)&wi[k][ty4];
#pragma unroll
                for (int j = 0; j < 4; ++j) {
                    float xv = (kz == 0) ? xq[j].x :
                               (kz == 1) ? xq[j].y :
                               (kz == 2) ? xq[j].z : xq[j].w;
                    unsigned long long x2 = packdup(xv);
                    fma2(accR[j][0], x2, wrv.x);
                    fma2(accR[j][1], x2, wrv.y);
                    fma2(accI[j][0], x2, wiv.x);
                    fma2(accI[j][1], x2, wiv.y);
                }
            }
        }
    }

    // ---- fused epilogue: mags + phase ----
    const size_t phoff = (size_t)NB * CR * NT;
#pragma unroll
    for (int j = 0; j < 4; ++j) {
        int t = t0 + tx + 16 * j;
        if (t >= NT) continue;
#pragma unroll
        for (int p = 0; p < 2; ++p) {
            float2 rv = unpack2(accR[j][p]);
            float2 iv = unpack2(accI[j][p]);
            float rr[2] = {rv.x, rv.y};
            float ii[2] = {iv.x, iv.y};
#pragma unroll
            for (int m = 0; m < 2; ++m) {
                int c = c0 + ty4 + p * 2 + m;
                if (c < CR) {
                    size_t o = ((size_t)b * CR + c) * (size_t)NT + (size_t)t;
                    float r_ = rr[m], i_ = ii[m];
                    out[o]         = sqrtf(fmaxf(r_ * r_ + i_ * i_, EPSV));
                    out[phoff + o] = atan2f(i_ + EPSV, r_ + EPSV);
                }
            }
        }
    }
}

extern "C" void kernel_launch(void* const* d_in, const int* in_sizes, int n_in,
                              void* d_out, int out_size) {
    const float* inp = (const float*)d_in[0];   // (16, 160000) fp32
    const float* wgt = (const float*)d_in[1];   // (514, 1, 400) fp32
    float* out = (float*)d_out;                 // mags ++ phase, fp32

    dim3 grid((NT + BT - 1) / BT,               // 26 frame tiles
              (CR + BCH - 1) / BCH,             // 5 channel tiles
              NB);                              // 16 batches
    convstft_kernel<<<grid, 256>>>(inp, wgt, out);
}